// round 13
// baseline (speedup 1.0000x reference)
#include <cuda_runtime.h>

// Problem constants (fixed shapes per reference)
#define B_    16
#define CIN_  128
#define COUT_ 3
#define WDIM_ 512
#define HW_   65536           // 256*256
#define HW4_  16384           // HW/4 (float4 granularity)

// Scratch for per-batch fused coefficients: coef[b][o][i] = style[b][i] * weight[o][i]
__device__ float g_coef[B_ * COUT_ * CIN_];

// ---------------------------------------------------------------------------
// Kernel 1 (tiny): style[b,c] = dot(w[b,:], affine_w[c,:]) + affine_b[c]
//                  coef[b,o,c] = style[b,c] * weight[o,c]
// grid = B_, block = CIN_ (one thread per channel)
// ---------------------------------------------------------------------------
__global__ void coef_kernel(const float* __restrict__ w,
                            const float* __restrict__ weight,
                            const float* __restrict__ affine_w,
                            const float* __restrict__ affine_b) {
    const int b = blockIdx.x;
    const int c = threadIdx.x;

    const float4* wb = reinterpret_cast<const float4*>(w + (size_t)b * WDIM_);
    const float4* aw = reinterpret_cast<const float4*>(affine_w + (size_t)c * WDIM_);

    float s = 0.0f;
    #pragma unroll 4
    for (int d = 0; d < WDIM_ / 4; d++) {
        float4 a = aw[d];
        float4 v = wb[d];
        s += a.x * v.x + a.y * v.y + a.z * v.z + a.w * v.w;
    }
    s += affine_b[c];

    #pragma unroll
    for (int o = 0; o < COUT_; o++) {
        g_coef[((size_t)b * COUT_ + o) * CIN_ + c] = s * weight[o * CIN_ + c];
    }
}

// ---------------------------------------------------------------------------
// Kernel 2 (streaming): out[b,o,hw] = sum_i x[b,i,hw] * coef[b,o,i] + bias[o]
// Each thread processes one float4 (4 pixels) across all 128 input channels.
// grid = (HW4_/256, B_), block = 256
// ---------------------------------------------------------------------------
__global__ __launch_bounds__(256)
void torgb_kernel(const float* __restrict__ x,
                  const float* __restrict__ bias,
                  float* __restrict__ out) {
    const int b = blockIdx.y;
    const int p = blockIdx.x * 256 + threadIdx.x;   // float4 index in the HW plane

    // Stage this batch's 384 coefficients in shared memory (broadcast reads later)
    __shared__ float sc[COUT_ * CIN_];
    for (int t = threadIdx.x; t < COUT_ * CIN_; t += 256)
        sc[t] = g_coef[(size_t)b * COUT_ * CIN_ + t];
    __syncthreads();

    const float4* xb = reinterpret_cast<const float4*>(x)
                       + (size_t)b * CIN_ * HW4_ + p;

    const float b0 = bias[0], b1 = bias[1], b2 = bias[2];
    float4 a0 = make_float4(b0, b0, b0, b0);
    float4 a1 = make_float4(b1, b1, b1, b1);
    float4 a2 = make_float4(b2, b2, b2, b2);

    #pragma unroll 8
    for (int i = 0; i < CIN_; i++) {
        float4 v = xb[(size_t)i * HW4_];
        const float c0 = sc[0 * CIN_ + i];
        const float c1 = sc[1 * CIN_ + i];
        const float c2 = sc[2 * CIN_ + i];
        a0.x += v.x * c0; a0.y += v.y * c0; a0.z += v.z * c0; a0.w += v.w * c0;
        a1.x += v.x * c1; a1.y += v.y * c1; a1.z += v.z * c1; a1.w += v.w * c1;
        a2.x += v.x * c2; a2.y += v.y * c2; a2.z += v.z * c2; a2.w += v.w * c2;
    }

    float4* ob = reinterpret_cast<float4*>(out) + (size_t)b * COUT_ * HW4_ + p;
    ob[0 * HW4_] = a0;
    ob[1 * HW4_] = a1;
    ob[2 * HW4_] = a2;
}

// ---------------------------------------------------------------------------
// Launch. Inputs in metadata order: x, w, weight, bias, affine_w, affine_b
// ---------------------------------------------------------------------------
extern "C" void kernel_launch(void* const* d_in, const int* in_sizes, int n_in,
                              void* d_out, int out_size) {
    const float* x        = (const float*)d_in[0];
    const float* w        = (const float*)d_in[1];
    const float* weight   = (const float*)d_in[2];
    const float* bias     = (const float*)d_in[3];
    const float* affine_w = (const float*)d_in[4];
    const float* affine_b = (const float*)d_in[5];
    float* out = (float*)d_out;

    coef_kernel<<<B_, CIN_>>>(w, weight, affine_w, affine_b);

    dim3 grid(HW4_ / 256, B_);
    torgb_kernel<<<grid, 256>>>(x, bias, out);
}

// round 14
// speedup vs baseline: 1.3040x; 1.3040x over previous
#include <cuda_runtime.h>

// Problem constants (fixed shapes per reference)
#define B_    16
#define CIN_  128
#define COUT_ 3
#define WDIM_ 512
#define HW_   65536           // 256*256
#define HW4_  16384           // HW/4 (float4 granularity)

// Scratch: coef[b][o][i] = style[b][i] * weight[o][i]
__device__ float g_coef[B_ * COUT_ * CIN_];

// ---------------------------------------------------------------------------
// Kernel 1: one WARP per (b,c) dot product (2048 warps total).
//   style[b,c] = dot(w[b,:], affine_w[c,:]) + affine_b[c]
//   coef[b,o,c] = style[b,c] * weight[o,c]
// grid = 256 blocks x 256 threads (8 warps/block).
// Lane loads are coalesced float4s: lane reads f4 indices {lane, lane+32,
// lane+64, lane+96} of the 128 float4s per 512-elem row.
// ---------------------------------------------------------------------------
__global__ __launch_bounds__(256)
void coef_kernel(const float* __restrict__ w,
                 const float* __restrict__ weight,
                 const float* __restrict__ affine_w,
                 const float* __restrict__ affine_b) {
    const int warp = (blockIdx.x * blockDim.x + threadIdx.x) >> 5;
    const int lane = threadIdx.x & 31;
    const int b = warp >> 7;        // warp / 128
    const int c = warp & 127;       // warp % 128

    const float4* wb = reinterpret_cast<const float4*>(w + (size_t)b * WDIM_);
    const float4* aw = reinterpret_cast<const float4*>(affine_w + (size_t)c * WDIM_);

    float s = 0.0f;
    #pragma unroll
    for (int k = 0; k < 4; k++) {
        float4 a = aw[lane + k * 32];
        float4 v = wb[lane + k * 32];
        s += a.x * v.x + a.y * v.y + a.z * v.z + a.w * v.w;
    }
    // warp tree reduce
    #pragma unroll
    for (int off = 16; off > 0; off >>= 1)
        s += __shfl_down_sync(0xFFFFFFFFu, s, off);

    if (lane == 0) {
        s += affine_b[c];
        #pragma unroll
        for (int o = 0; o < COUT_; o++)
            g_coef[((size_t)b * COUT_ + o) * CIN_ + c] = s * weight[o * CIN_ + c];
    }
}

// ---------------------------------------------------------------------------
// Kernel 2 (streaming): out[b,o,hw] = sum_i x[b,i,hw]*coef[b,o,i] + bias[o]
// Channel-split for occupancy: each block = 128 float4-pixels x 2 channel
// halves. Thread (half, lp) reduces 64 channels for pixel-group lp; half 1
// deposits partials in smem, half 0 combines + stores.
// grid = (HW4_/128, B_) = (128, 16), block = 256  -> 16384 warps total.
// ---------------------------------------------------------------------------
__global__ __launch_bounds__(256)
void torgb_kernel(const float* __restrict__ x,
                  const float* __restrict__ bias,
                  float* __restrict__ out) {
    const int b    = blockIdx.y;
    const int tid  = threadIdx.x;
    const int half = tid >> 7;          // 0 or 1
    const int lp   = tid & 127;         // local pixel-group
    const int p    = blockIdx.x * 128 + lp;

    __shared__ float sc[COUT_ * CIN_];              // 384 coefs for this batch
    __shared__ float part[128][13];                 // 12 partials + pad (conflict-free)

    for (int t = tid; t < COUT_ * CIN_; t += 256)
        sc[t] = g_coef[(size_t)b * COUT_ * CIN_ + t];
    __syncthreads();

    const float4* xb = reinterpret_cast<const float4*>(x)
                       + ((size_t)b * CIN_ + half * 64) * HW4_ + p;

    float4 a0 = make_float4(0.f, 0.f, 0.f, 0.f);
    float4 a1 = a0, a2 = a0;

    const int cbase = half * 64;
    #pragma unroll 8
    for (int i = 0; i < 64; i++) {
        float4 v = __ldcs(&xb[(size_t)i * HW4_]);
        const float c0 = sc[0 * CIN_ + cbase + i];
        const float c1 = sc[1 * CIN_ + cbase + i];
        const float c2 = sc[2 * CIN_ + cbase + i];
        a0.x += v.x * c0; a0.y += v.y * c0; a0.z += v.z * c0; a0.w += v.w * c0;
        a1.x += v.x * c1; a1.y += v.y * c1; a1.z += v.z * c1; a1.w += v.w * c1;
        a2.x += v.x * c2; a2.y += v.y * c2; a2.z += v.z * c2; a2.w += v.w * c2;
    }

    if (half == 1) {
        part[lp][0] = a0.x; part[lp][1]  = a0.y; part[lp][2]  = a0.z; part[lp][3]  = a0.w;
        part[lp][4] = a1.x; part[lp][5]  = a1.y; part[lp][6]  = a1.z; part[lp][7]  = a1.w;
        part[lp][8] = a2.x; part[lp][9]  = a2.y; part[lp][10] = a2.z; part[lp][11] = a2.w;
    }
    __syncthreads();

    if (half == 0) {
        const float b0 = bias[0], b1 = bias[1], b2 = bias[2];
        a0.x += part[lp][0] + b0; a0.y += part[lp][1]  + b0;
        a0.z += part[lp][2] + b0; a0.w += part[lp][3]  + b0;
        a1.x += part[lp][4] + b1; a1.y += part[lp][5]  + b1;
        a1.z += part[lp][6] + b1; a1.w += part[lp][7]  + b1;
        a2.x += part[lp][8] + b2; a2.y += part[lp][9]  + b2;
        a2.z += part[lp][10]+ b2; a2.w += part[lp][11] + b2;

        float4* ob = reinterpret_cast<float4*>(out)
                     + (size_t)b * COUT_ * HW4_ + p;
        __stcs(&ob[0 * HW4_], a0);
        __stcs(&ob[1 * HW4_], a1);
        __stcs(&ob[2 * HW4_], a2);
    }
}

// ---------------------------------------------------------------------------
// Launch. Inputs in metadata order: x, w, weight, bias, affine_w, affine_b
// ---------------------------------------------------------------------------
extern "C" void kernel_launch(void* const* d_in, const int* in_sizes, int n_in,
                              void* d_out, int out_size) {
    const float* x        = (const float*)d_in[0];
    const float* w        = (const float*)d_in[1];
    const float* weight   = (const float*)d_in[2];
    const float* bias     = (const float*)d_in[3];
    const float* affine_w = (const float*)d_in[4];
    const float* affine_b = (const float*)d_in[5];
    float* out = (float*)d_out;

    coef_kernel<<<256, 256>>>(w, weight, affine_w, affine_b);

    dim3 grid(HW4_ / 128, B_);
    torgb_kernel<<<grid, 256>>>(x, bias, out);
}

// round 15
// speedup vs baseline: 1.3228x; 1.0144x over previous
#include <cuda_runtime.h>

// Problem constants (fixed shapes per reference)
#define B_    16
#define CIN_  128
#define COUT_ 3
#define WDIM_ 512
#define HW_   65536           // 256*256
#define HW4_  16384           // HW/4 (float4 granularity)

// Scratch: coef[b][o][i] = style[b][i] * weight[o][i]
__device__ float g_coef[B_ * COUT_ * CIN_];

// ---------------------------------------------------------------------------
// Kernel 1: one WARP per (b,c) dot product (2048 warps total).
// ---------------------------------------------------------------------------
__global__ __launch_bounds__(256)
void coef_kernel(const float* __restrict__ w,
                 const float* __restrict__ weight,
                 const float* __restrict__ affine_w,
                 const float* __restrict__ affine_b) {
    const int warp = (blockIdx.x * blockDim.x + threadIdx.x) >> 5;
    const int lane = threadIdx.x & 31;
    const int b = warp >> 7;        // warp / 128
    const int c = warp & 127;       // warp % 128

    const float4* wb = reinterpret_cast<const float4*>(w + (size_t)b * WDIM_);
    const float4* aw = reinterpret_cast<const float4*>(affine_w + (size_t)c * WDIM_);

    float s = 0.0f;
    #pragma unroll
    for (int k = 0; k < 4; k++) {
        float4 a = aw[lane + k * 32];
        float4 v = wb[lane + k * 32];
        s += a.x * v.x + a.y * v.y + a.z * v.z + a.w * v.w;
    }
    #pragma unroll
    for (int off = 16; off > 0; off >>= 1)
        s += __shfl_down_sync(0xFFFFFFFFu, s, off);

    if (lane == 0) {
        s += affine_b[c];
        #pragma unroll
        for (int o = 0; o < COUT_; o++)
            g_coef[((size_t)b * COUT_ + o) * CIN_ + c] = s * weight[o * CIN_ + c];
    }
}

// ---------------------------------------------------------------------------
// Kernel 2 (streaming): out[b,o,hw] = sum_i x[b,i,hw]*coef[b,o,i] + bias[o]
// Channel-split (64 ch per thread) for warp count; __launch_bounds__(256,7)
// caps regs at 36 -> 7 blocks/SM = 56 warps/SM (was 5 blocks / 40 warps).
// grid = (HW4_/128, B_) = (128, 16), block = 256.
// ---------------------------------------------------------------------------
__global__ void __launch_bounds__(256, 7)
torgb_kernel(const float* __restrict__ x,
             const float* __restrict__ bias,
             float* __restrict__ out) {
    const int b    = blockIdx.y;
    const int tid  = threadIdx.x;
    const int half = tid >> 7;          // 0 or 1
    const int lp   = tid & 127;         // local pixel-group
    const int p    = blockIdx.x * 128 + lp;

    __shared__ float sc[COUT_ * CIN_];              // 384 coefs for this batch
    __shared__ float part[128][13];                 // 12 partials + pad

    for (int t = tid; t < COUT_ * CIN_; t += 256)
        sc[t] = g_coef[(size_t)b * COUT_ * CIN_ + t];
    __syncthreads();

    const float4* xb = reinterpret_cast<const float4*>(x)
                       + ((size_t)b * CIN_ + half * 64) * HW4_ + p;

    float4 a0 = make_float4(0.f, 0.f, 0.f, 0.f);
    float4 a1 = a0, a2 = a0;

    const int cbase = half * 64;
    #pragma unroll 4
    for (int i = 0; i < 64; i++) {
        float4 v = __ldcs(&xb[(size_t)i * HW4_]);
        const float c0 = sc[0 * CIN_ + cbase + i];
        const float c1 = sc[1 * CIN_ + cbase + i];
        const float c2 = sc[2 * CIN_ + cbase + i];
        a0.x += v.x * c0; a0.y += v.y * c0; a0.z += v.z * c0; a0.w += v.w * c0;
        a1.x += v.x * c1; a1.y += v.y * c1; a1.z += v.z * c1; a1.w += v.w * c1;
        a2.x += v.x * c2; a2.y += v.y * c2; a2.z += v.z * c2; a2.w += v.w * c2;
    }

    if (half == 1) {
        part[lp][0] = a0.x; part[lp][1]  = a0.y; part[lp][2]  = a0.z; part[lp][3]  = a0.w;
        part[lp][4] = a1.x; part[lp][5]  = a1.y; part[lp][6]  = a1.z; part[lp][7]  = a1.w;
        part[lp][8] = a2.x; part[lp][9]  = a2.y; part[lp][10] = a2.z; part[lp][11] = a2.w;
    }
    __syncthreads();

    if (half == 0) {
        const float b0 = bias[0], b1 = bias[1], b2 = bias[2];
        a0.x += part[lp][0] + b0; a0.y += part[lp][1]  + b0;
        a0.z += part[lp][2] + b0; a0.w += part[lp][3]  + b0;
        a1.x += part[lp][4] + b1; a1.y += part[lp][5]  + b1;
        a1.z += part[lp][6] + b1; a1.w += part[lp][7]  + b1;
        a2.x += part[lp][8] + b2; a2.y += part[lp][9]  + b2;
        a2.z += part[lp][10]+ b2; a2.w += part[lp][11] + b2;

        float4* ob = reinterpret_cast<float4*>(out)
                     + (size_t)b * COUT_ * HW4_ + p;
        __stcs(&ob[0 * HW4_], a0);
        __stcs(&ob[1 * HW4_], a1);
        __stcs(&ob[2 * HW4_], a2);
    }
}

// ---------------------------------------------------------------------------
// Launch. Inputs in metadata order: x, w, weight, bias, affine_w, affine_b
// ---------------------------------------------------------------------------
extern "C" void kernel_launch(void* const* d_in, const int* in_sizes, int n_in,
                              void* d_out, int out_size) {
    const float* x        = (const float*)d_in[0];
    const float* w        = (const float*)d_in[1];
    const float* weight   = (const float*)d_in[2];
    const float* bias     = (const float*)d_in[3];
    const float* affine_w = (const float*)d_in[4];
    const float* affine_b = (const float*)d_in[5];
    float* out = (float*)d_out;

    coef_kernel<<<256, 256>>>(w, weight, affine_w, affine_b);

    dim3 grid(HW4_ / 128, B_);
    torgb_kernel<<<grid, 256>>>(x, bias, out);
}